// round 16
// baseline (speedup 1.0000x reference)
#include <cuda_runtime.h>
#include <cooperative_groups.h>
#include <math.h>
#include <stdint.h>

namespace cg = cooperative_groups;

#define NB 16
#define NT 2048
#define NC 256
#define NF 256
#define NU 512
#define NMEL 80
#define NOUTC 592           // 2*NC + NMEL
#define KTOT 768            // NC * 3 taps
#define BK 8
#define NCHUNK (KTOT / BK)  // 96
#define UM2CAP 8192
#define EPS 1e-5f
#define AP 136              // As row pad (136%32=8 -> conflict-free frag loads)
#define BP 72               // Bs row pad (72%32=8)

// ---------------- static device scratch ----------------
__device__ int   g_starts[NB*NU];
__device__ int   g_dur[NB*NU];
__device__ int   g_nseg[NB];
__device__ int   g_umax;
__device__ float g_cgv[NB*NC];
__device__ float g_uc[NB*NC*NU];
__device__ float g_up[NB*NC*NU];
__device__ float g_x0[NB*NC*NU];        // conv1 input: (u_c + cond) * mask
__device__ float g_x1[NB*NF*NU];        // LN1 output * mask  -> conv2 input
__device__ int   g_dpred[NB*NU];
__device__ int   g_um2[NB*UM2CAP];

__device__ __forceinline__ unsigned f2tf32(float x) {
    unsigned r; asm("cvt.rna.tf32.f32 %0, %1;" : "=r"(r) : "f"(x)); return r;
}
__device__ __forceinline__ void mma_tf32(float* c, const unsigned* a,
                                         unsigned b0, unsigned b1) {
    asm("mma.sync.aligned.m16n8k8.row.col.f32.tf32.tf32.f32 "
        "{%0,%1,%2,%3}, {%4,%5,%6,%7}, {%8,%9}, {%0,%1,%2,%3};"
        : "+f"(c[0]), "+f"(c[1]), "+f"(c[2]), "+f"(c[3])
        : "r"(a[0]), "r"(a[1]), "r"(a[2]), "r"(a[3]), "r"(b0), "r"(b1));
}

// ---------------- kernel 1: fused dedup (blocks 0..15) + cond (blocks 16..31) ----------------
__global__ __launch_bounds__(1024) void k_prep(const int* __restrict__ ph,
                                               const float* __restrict__ g,
                                               const float* __restrict__ cw,
                                               const float* __restrict__ cb) {
    int blk = blockIdx.x;
    if (blk < NB) {
        int b = blk;
        const int* p = ph + (size_t)b * NT;
        int tid = threadIdx.x;
        int lane = tid & 31, wid = tid >> 5;
        int i0 = 2 * tid, i1 = 2 * tid + 1;
        int p0 = p[i0], p1 = p[i1];
        int pm1 = (i0 > 0) ? p[i0 - 1] : 0;
        int f0 = (i0 == 0) || (p0 != pm1);
        int f1 = (p1 != p0);
        int tsum = f0 + f1;
        int ws = tsum;
        #pragma unroll
        for (int o = 1; o < 32; o <<= 1) {
            int y = __shfl_up_sync(0xffffffffu, ws, o);
            if (lane >= o) ws += y;
        }
        __shared__ int wt[32];
        if (lane == 31) wt[wid] = ws;
        __syncthreads();
        if (wid == 0) {
            int t = wt[lane];
            #pragma unroll
            for (int o = 1; o < 32; o <<= 1) {
                int y = __shfl_up_sync(0xffffffffu, t, o);
                if (lane >= o) t += y;
            }
            wt[lane] = t;
        }
        __syncthreads();
        int base = (wid ? wt[wid - 1] : 0) + (ws - tsum);
        int incl0 = base + f0;
        int incl1 = base + f0 + f1;
        if (f0) g_starts[b * NU + incl0 - 1] = i0;
        if (f1) g_starts[b * NU + incl1 - 1] = i1;
        int ns = wt[31];
        __syncthreads();
        for (int u = tid; u < NU; u += 1024) {
            if (u < ns) {
                int st = g_starts[b * NU + u];
                int en = (u + 1 < ns) ? g_starts[b * NU + u + 1] : NT;
                g_dur[b * NU + u] = en - st;
            } else {
                g_dur[b * NU + u] = 0;
            }
        }
        if (tid == 0) g_nseg[b] = ns;
    } else {
        int b = blk - NB;
        int c = threadIdx.x;
        __shared__ float gs[NC];
        if (c < NC) gs[c] = g[(size_t)b * NC + c];
        __syncthreads();
        if (c < NC) {
            float acc = 0.f;
            const float* row = cw + (size_t)c * NC;
            #pragma unroll 8
            for (int gi = 0; gi < NC; gi++) acc += row[gi] * gs[gi];
            g_cgv[b * NC + c] = acc + cb[c];
        }
    }
}

// ---------------- kernel 2: mean pool (4 channels / block) ----------------
__global__ __launch_bounds__(256) void k_pool(const float* __restrict__ ec,
                                              const float* __restrict__ ep) {
    int b  = blockIdx.y;
    int c0 = blockIdx.x * 4;
    bool isC = (c0 < NC);
    const float* base = isC ? ec + ((size_t)b * NC + c0) * NT
                            : ep + ((size_t)b * NC + (c0 - NC)) * NT;
    __shared__ float rows[4][NT];
    const float4* s4 = (const float4*)base;
    float4* r4 = (float4*)&rows[0][0];
    #pragma unroll
    for (int i = threadIdx.x; i < 4 * NT / 4; i += 256) r4[i] = s4[i];
    __syncthreads();
    int ns = g_nseg[b];
    for (int u = threadIdx.x; u < NU; u += 256) {
        float m[4] = {0.f, 0.f, 0.f, 0.f};
        if (u < ns) {
            int st = g_starts[b * NU + u];
            int d  = g_dur[b * NU + u];
            float inv = 1.f / (float)d;
            #pragma unroll
            for (int r = 0; r < 4; r++) {
                float s = 0.f;
                for (int i = 0; i < d; i++) s += rows[r][st + i];
                m[r] = s * inv;
            }
        }
        #pragma unroll
        for (int r = 0; r < 4; r++) {
            int cc = c0 + r;
            if (isC) {
                float cond = g_cgv[b * NC + cc];
                g_uc[((size_t)b * NC + cc) * NU + u] = m[r];
                g_x0[((size_t)b * NC + cc) * NU + u] = (u < ns) ? (m[r] + cond) : 0.f;
            } else {
                g_up[((size_t)b * NC + (cc - NC)) * NU + u] = m[r];
            }
        }
    }
}

// ---------------- conv GEMM via 3xTF32 mma.sync, M-split 2-CTA cluster ----------------
// Cluster (2,1,1): rank owns rows rank*128..+127 of a 64-col tile (u0=(bx>>1)*64).
// Per CTA: 8 warps, warp w: rows rank*128 + w*16..+15 (1 m16 frag), 64 cols (8 n8).
// Column LN/proj sums exchanged with the peer CTA via DSMEM.
// PHASE 0: X=g_x0, epilogue = bias+relu+LN1*mask -> g_x1 (own half rows)
// PHASE 1: X=g_x1, epilogue = bias+relu+LN2*mask -> proj -> ceil -> g_dpred
template<int PHASE>
__global__ __launch_bounds__(256, 2) __cluster_dims__(2, 1, 1)
void k_conv(const float* __restrict__ W,
            const float* __restrict__ bias,
            const float* __restrict__ gamma,
            const float* __restrict__ beta,
            const float* __restrict__ pw,
            const float* __restrict__ pb) {
    __shared__ float Ah[2][BK][AP];
    __shared__ float Al[2][BK][AP];
    __shared__ float Bh[2][BK][BP];
    __shared__ float Bl[2][BK][BP];
    __shared__ float redA[8][64];
    __shared__ float redB[8][64];
    __shared__ float p1[64], p2[64];     // half-column partial sums (exchanged)
    __shared__ float pd[64];             // proj partial (phase 1 exchange)
    __shared__ float mvs[64], rvs[64];

    cg::cluster_group cluster = cg::this_cluster();
    unsigned rank = cluster.block_rank();
    unsigned peer = rank ^ 1u;

    int b  = blockIdx.y;
    int u0 = (blockIdx.x >> 1) * 64;
    int rbase = rank * 128;
    int tid = threadIdx.x;
    int w  = tid >> 5;
    int l  = tid & 31;
    int gq = l >> 2;        // 0..7
    int tq = l & 3;         // 0..3
    const float* X = PHASE ? g_x1 : g_x0;
    const float* Xb = X + (size_t)b * NC * NU;

    float acc[8][4];
    #pragma unroll
    for (int j = 0; j < 8; j++)
        #pragma unroll
        for (int r = 0; r < 4; r++) acc[j][r] = 0.f;

    // loaders: A: am=tid&127 (row in half), akh=tid>>7 (k-quad); B: bkk=tid>>5, bnn=(tid&31)*2
    int am  = tid & 127;
    int akh = tid >> 7;
    int bkk = tid >> 5;
    int bnn = (tid & 31) * 2;
    float4 aA;
    float  bv0, bv1;

    auto loadG = [&](int k0) {
        aA = *(const float4*)&W[(size_t)(rbase + am) * KTOT + k0 + akh * 4];
        int kg  = k0 + bkk;
        int c   = kg / 3;
        int tap = kg - 3 * c;
        const float* xr = Xb + (size_t)c * NU;
        int col = u0 + bnn + tap - 1;
        bv0 = (col >= 0 && col < NU) ? xr[col] : 0.f;
        int col1 = col + 1;
        bv1 = (col1 >= 0 && col1 < NU) ? xr[col1] : 0.f;
    };
    auto storeS = [&](int buf) {
        float wv[4] = {aA.x, aA.y, aA.z, aA.w};
        #pragma unroll
        for (int q = 0; q < 4; q++) {
            float hf = __uint_as_float(f2tf32(wv[q]));
            float lf = __uint_as_float(f2tf32(wv[q] - hf));
            Ah[buf][akh * 4 + q][am] = hf;
            Al[buf][akh * 4 + q][am] = lf;
        }
        float h0 = __uint_as_float(f2tf32(bv0));
        float l0 = __uint_as_float(f2tf32(bv0 - h0));
        float h1 = __uint_as_float(f2tf32(bv1));
        float l1 = __uint_as_float(f2tf32(bv1 - h1));
        Bh[buf][bkk][bnn] = h0;  Bh[buf][bkk][bnn + 1] = h1;
        Bl[buf][bkk][bnn] = l0;  Bl[buf][bkk][bnn + 1] = l1;
    };

    loadG(0);
    storeS(0);
    __syncthreads();

    for (int chunk = 0; chunk < NCHUNK; chunk++) {
        int buf = chunk & 1;
        if (chunk + 1 < NCHUNK) loadG((chunk + 1) * BK);

        unsigned ah[4], al[4];
        {
            int mb = w * 16 + gq;
            ah[0] = __float_as_uint(Ah[buf][tq][mb]);
            ah[1] = __float_as_uint(Ah[buf][tq][mb + 8]);
            ah[2] = __float_as_uint(Ah[buf][tq + 4][mb]);
            ah[3] = __float_as_uint(Ah[buf][tq + 4][mb + 8]);
            al[0] = __float_as_uint(Al[buf][tq][mb]);
            al[1] = __float_as_uint(Al[buf][tq][mb + 8]);
            al[2] = __float_as_uint(Al[buf][tq + 4][mb]);
            al[3] = __float_as_uint(Al[buf][tq + 4][mb + 8]);
        }
        #pragma unroll
        for (int j = 0; j < 8; j++) {
            int nb = j * 8 + gq;
            unsigned bh0 = __float_as_uint(Bh[buf][tq][nb]);
            unsigned bh1 = __float_as_uint(Bh[buf][tq + 4][nb]);
            unsigned bl0 = __float_as_uint(Bl[buf][tq][nb]);
            unsigned bl1 = __float_as_uint(Bl[buf][tq + 4][nb]);
            mma_tf32(acc[j], ah, bh0, bh1);
            mma_tf32(acc[j], ah, bl0, bl1);
            mma_tf32(acc[j], al, bh0, bh1);
        }
        if (chunk + 1 < NCHUNK) storeS(buf ^ 1);
        __syncthreads();
    }

    // ---- epilogue ----
    // thread rows: f0 = rbase + w*16 + gq, f1 = f0 + 8; cols: j*8 + 2*tq + {0,1}
    float bs0 = bias[rbase + w * 16 + gq];
    float bs1 = bias[rbase + w * 16 + gq + 8];
    float s1[8][2], s2[8][2];
    #pragma unroll
    for (int j = 0; j < 8; j++) { s1[j][0] = s1[j][1] = s2[j][0] = s2[j][1] = 0.f; }
    #pragma unroll
    for (int j = 0; j < 8; j++) {
        float x0 = fmaxf(acc[j][0] + bs0, 0.f);
        float x1 = fmaxf(acc[j][1] + bs0, 0.f);
        float x2 = fmaxf(acc[j][2] + bs1, 0.f);
        float x3 = fmaxf(acc[j][3] + bs1, 0.f);
        acc[j][0] = x0; acc[j][1] = x1; acc[j][2] = x2; acc[j][3] = x3;
        s1[j][0] += x0 + x2;  s1[j][1] += x1 + x3;
        s2[j][0] += x0 * x0 + x2 * x2;
        s2[j][1] += x1 * x1 + x3 * x3;
    }
    #pragma unroll
    for (int o = 4; o < 32; o <<= 1) {
        #pragma unroll
        for (int j = 0; j < 8; j++) {
            s1[j][0] += __shfl_xor_sync(0xffffffffu, s1[j][0], o);
            s1[j][1] += __shfl_xor_sync(0xffffffffu, s1[j][1], o);
            s2[j][0] += __shfl_xor_sync(0xffffffffu, s2[j][0], o);
            s2[j][1] += __shfl_xor_sync(0xffffffffu, s2[j][1], o);
        }
    }
    if (l < 4) {
        #pragma unroll
        for (int j = 0; j < 8; j++) {
            redA[w][j * 8 + 2 * l]     = s1[j][0];
            redA[w][j * 8 + 2 * l + 1] = s1[j][1];
            redB[w][j * 8 + 2 * l]     = s2[j][0];
            redB[w][j * 8 + 2 * l + 1] = s2[j][1];
        }
    }
    __syncthreads();
    if (tid < 64) {
        float S1 = 0.f, S2 = 0.f;
        #pragma unroll
        for (int q = 0; q < 8; q++) { S1 += redA[q][tid]; S2 += redB[q][tid]; }
        p1[tid] = S1;
        p2[tid] = S2;
    }
    cluster.sync();
    if (tid < 64) {
        const float* pp1 = cluster.map_shared_rank(p1, peer);
        const float* pp2 = cluster.map_shared_rank(p2, peer);
        float S1 = p1[tid] + pp1[tid];
        float S2 = p2[tid] + pp2[tid];
        float m  = S1 * (1.f / 256.f);
        float vv = S2 * (1.f / 256.f) - m * m;
        mvs[tid] = m;
        rvs[tid] = 1.f / sqrtf(vv + EPS);
    }
    __syncthreads();

    int ns = g_nseg[b];
    float mn[8][2], rv[8][2], mk[8][2];
    #pragma unroll
    for (int j = 0; j < 8; j++) {
        int c0 = j * 8 + 2 * tq;
        mn[j][0] = mvs[c0];     mn[j][1] = mvs[c0 + 1];
        rv[j][0] = rvs[c0];     rv[j][1] = rvs[c0 + 1];
        mk[j][0] = (u0 + c0 < ns) ? 1.f : 0.f;
        mk[j][1] = (u0 + c0 + 1 < ns) ? 1.f : 0.f;
    }

    if (PHASE == 0) {
        int f0 = rbase + w * 16 + gq;
        float ga0 = gamma[f0], be0 = beta[f0];
        float ga1 = gamma[f0 + 8], be1 = beta[f0 + 8];
        #pragma unroll
        for (int j = 0; j < 8; j++) {
            int cc = u0 + j * 8 + 2 * tq;
            float o0 = ((acc[j][0] - mn[j][0]) * rv[j][0] * ga0 + be0) * mk[j][0];
            float o1 = ((acc[j][1] - mn[j][1]) * rv[j][1] * ga0 + be0) * mk[j][1];
            float o2 = ((acc[j][2] - mn[j][0]) * rv[j][0] * ga1 + be1) * mk[j][0];
            float o3 = ((acc[j][3] - mn[j][1]) * rv[j][1] * ga1 + be1) * mk[j][1];
            *(float2*)&g_x1[((size_t)b * NF + f0) * NU + cc]     = make_float2(o0, o1);
            *(float2*)&g_x1[((size_t)b * NF + f0 + 8) * NU + cc] = make_float2(o2, o3);
        }
        cluster.sync();   // peer smem lifetime guard
    } else {
        float dp[8][2];
        #pragma unroll
        for (int j = 0; j < 8; j++) { dp[j][0] = 0.f; dp[j][1] = 0.f; }
        int f0 = rbase + w * 16 + gq;
        float ga0 = gamma[f0], be0 = beta[f0], pw0 = pw[f0];
        float ga1 = gamma[f0 + 8], be1 = beta[f0 + 8], pw1 = pw[f0 + 8];
        #pragma unroll
        for (int j = 0; j < 8; j++) {
            float n0 = ((acc[j][0] - mn[j][0]) * rv[j][0] * ga0 + be0) * mk[j][0];
            float n1 = ((acc[j][1] - mn[j][1]) * rv[j][1] * ga0 + be0) * mk[j][1];
            float n2 = ((acc[j][2] - mn[j][0]) * rv[j][0] * ga1 + be1) * mk[j][0];
            float n3 = ((acc[j][3] - mn[j][1]) * rv[j][1] * ga1 + be1) * mk[j][1];
            dp[j][0] += n0 * pw0 + n2 * pw1;
            dp[j][1] += n1 * pw0 + n3 * pw1;
        }
        #pragma unroll
        for (int o = 4; o < 32; o <<= 1) {
            #pragma unroll
            for (int j = 0; j < 8; j++) {
                dp[j][0] += __shfl_xor_sync(0xffffffffu, dp[j][0], o);
                dp[j][1] += __shfl_xor_sync(0xffffffffu, dp[j][1], o);
            }
        }
        if (l < 4) {
            #pragma unroll
            for (int j = 0; j < 8; j++) {
                redA[w][j * 8 + 2 * l]     = dp[j][0];
                redA[w][j * 8 + 2 * l + 1] = dp[j][1];
            }
        }
        __syncthreads();
        if (tid < 64) {
            float S = 0.f;
            #pragma unroll
            for (int q = 0; q < 8; q++) S += redA[q][tid];
            pd[tid] = S;
        }
        cluster.sync();
        if (rank == 0 && tid < 64) {
            const float* ppd = cluster.map_shared_rank(pd, peer);
            float S = pd[tid] + ppd[tid];
            int u = u0 + tid;
            float d = (u < ns) ? ceilf(S + pb[0]) : 0.f;
            g_dpred[b * NU + u] = (int)d;
        }
        cluster.sync();   // peer smem lifetime guard
    }
}

// ---------------- kernel 5: zero um2 row + umax + per-batch prefix scan + scatter ----------------
__global__ __launch_bounds__(512) void k_scan(int Tn) {
    int b = blockIdx.x;
    for (int p = threadIdx.x; p < Tn; p += 512)
        g_um2[b * Tn + p] = 0;
    if (b == 0 && threadIdx.x == 0) {
        int mx = 0;
        #pragma unroll
        for (int q = 0; q < NB; q++) mx = max(mx, g_nseg[q]);
        g_umax = mx;
    }
    __syncthreads();
    int u = threadIdx.x;
    int lane = u & 31, wid = u >> 5;
    int d = g_dpred[b * NU + u];
    int x = d;
    #pragma unroll
    for (int o = 1; o < 32; o <<= 1) {
        int y = __shfl_up_sync(0xffffffffu, x, o);
        if (lane >= o) x += y;
    }
    __shared__ int wt[16];
    if (lane == 31) wt[wid] = x;
    __syncthreads();
    if (u < 16) {
        int t = wt[u];
        #pragma unroll
        for (int o = 1; o < 16; o <<= 1) {
            int y = __shfl_up_sync(0xffffu, t, o);
            if (u >= o) t += y;
        }
        wt[u] = t;
    }
    __syncthreads();
    int csum = x + (wid ? wt[wid - 1] : 0);
    int prev = csum - d;
    int lo = prev > 0 ? prev : 0;
    int hi = csum < Tn ? csum : Tn;
    for (int p = lo; p < hi; p++)
        atomicAdd(&g_um2[b * Tn + p], u + 1);
}

// ---------------- kernel 6: expand + interp -> output ----------------
__global__ __launch_bounds__(256) void k_out(const float* __restrict__ mel,
                                             float* __restrict__ out,
                                             int Tn, int total) {
    int i = blockIdx.x * blockDim.x + threadIdx.x;
    if (i >= total) return;
    int perb = NOUTC * Tn;
    int b = i / perb;
    int r = i - b * perb;
    int ch = r / Tn;
    int t = r - ch * Tn;
    if (ch < 2 * NC) {
        int v = g_um2[b * Tn + t];
        int um = g_umax;
        int idx = v < um ? v : um;   // jax gather clamp semantics
        float val = 0.f;
        if (idx > 0) {
            const float* P = (ch < NC) ? g_uc : g_up;
            int c = (ch < NC) ? ch : ch - NC;
            val = P[((size_t)b * NC + c) * NU + idx - 1];
        }
        out[i] = val;
    } else {
        int mch = ch - 2 * NC;
        float scale = (float)(2048.0 / (double)Tn);
        float src = ((float)t + 0.5f) * scale - 0.5f;
        src = fminf(fmaxf(src, 0.f), (float)(NT - 1));
        int i0 = (int)floorf(src);
        int i1 = i0 + 1 < NT - 1 ? i0 + 1 : NT - 1;
        float w = src - (float)i0;
        const float* mr = mel + ((size_t)b * NMEL + mch) * NT;
        out[i] = mr[i0] * (1.f - w) + mr[i1] * w;
    }
}

// ---------------- launch ----------------
extern "C" void kernel_launch(void* const* d_in, const int* in_sizes, int n_in,
                              void* d_out, int out_size) {
    const float* emb_c  = (const float*)d_in[0];
    const float* emb_p  = (const float*)d_in[1];
    const float* mel    = (const float*)d_in[2];
    const float* g      = (const float*)d_in[3];
    const float* c1w    = (const float*)d_in[4];
    const float* c1b    = (const float*)d_in[5];
    const float* l1g    = (const float*)d_in[6];
    const float* l1b    = (const float*)d_in[7];
    const float* c2w    = (const float*)d_in[8];
    const float* c2b    = (const float*)d_in[9];
    const float* l2g    = (const float*)d_in[10];
    const float* l2b    = (const float*)d_in[11];
    const float* pw     = (const float*)d_in[12];
    const float* pb     = (const float*)d_in[13];
    const float* cw     = (const float*)d_in[14];
    const float* cb     = (const float*)d_in[15];
    const int*   ph     = (const int*)d_in[16];
    float* out = (float*)d_out;

    int Tn = out_size / (NB * NOUTC);

    k_prep<<<2 * NB, 1024>>>(ph, g, cw, cb);
    k_pool<<<dim3(2 * NC / 4, NB), 256>>>(emb_c, emb_p);
    k_conv<0><<<dim3(2 * NU / 64, NB), 256>>>(c1w, c1b, l1g, l1b, pw, pb);
    k_conv<1><<<dim3(2 * NU / 64, NB), 256>>>(c2w, c2b, l2g, l2b, pw, pb);
    k_scan<<<NB, NU>>>(Tn);
    k_out<<<(out_size + 255) / 256, 256>>>(mel, out, Tn, out_size);
}

// round 17
// speedup vs baseline: 1.0719x; 1.0719x over previous
#include <cuda_runtime.h>
#include <cooperative_groups.h>
#include <math.h>
#include <stdint.h>

namespace cg = cooperative_groups;

#define NB 16
#define NT 2048
#define NC 256
#define NF 256
#define NU 512
#define NMEL 80
#define NOUTC 592           // 2*NC + NMEL
#define KTOT 768            // NC * 3 taps
#define BK 8
#define NCHUNK (KTOT / BK)  // 96
#define UM2CAP 8192
#define EPS 1e-5f
#define AP 136              // As row pad (136%32=8 -> conflict-free frag loads)
#define BP 72               // Bs row pad (72%32=8)

// ---------------- static device scratch ----------------
__device__ int   g_starts[NB*NU];
__device__ int   g_dur[NB*NU];
__device__ int   g_nseg[NB];
__device__ int   g_umax;
__device__ float g_cgv[NB*NC];
__device__ float g_uc[NB*NC*NU];
__device__ float g_up[NB*NC*NU];
__device__ float g_x0[NB*NC*NU];        // conv1 input: (u_c + cond) * mask
__device__ float g_x1[NB*NF*NU];        // LN1 output * mask  -> conv2 input
__device__ int   g_dpred[NB*NU];
__device__ int   g_um2[NB*UM2CAP];

__device__ __forceinline__ unsigned f2tf32(float x) {
    unsigned r; asm("cvt.rna.tf32.f32 %0, %1;" : "=r"(r) : "f"(x)); return r;
}
__device__ __forceinline__ void mma_tf32(float* c, const unsigned* a,
                                         unsigned b0, unsigned b1) {
    asm("mma.sync.aligned.m16n8k8.row.col.f32.tf32.tf32.f32 "
        "{%0,%1,%2,%3}, {%4,%5,%6,%7}, {%8,%9}, {%0,%1,%2,%3};"
        : "+f"(c[0]), "+f"(c[1]), "+f"(c[2]), "+f"(c[3])
        : "r"(a[0]), "r"(a[1]), "r"(a[2]), "r"(a[3]), "r"(b0), "r"(b1));
}

// ---------------- kernel 1: fused dedup (blocks 0..15) + cond (blocks 16..31) ----------------
__global__ __launch_bounds__(1024) void k_prep(const int* __restrict__ ph,
                                               const float* __restrict__ g,
                                               const float* __restrict__ cw,
                                               const float* __restrict__ cb) {
    int blk = blockIdx.x;
    if (blk < NB) {
        int b = blk;
        const int* p = ph + (size_t)b * NT;
        int tid = threadIdx.x;
        int lane = tid & 31, wid = tid >> 5;
        int i0 = 2 * tid, i1 = 2 * tid + 1;
        int p0 = p[i0], p1 = p[i1];
        int pm1 = (i0 > 0) ? p[i0 - 1] : 0;
        int f0 = (i0 == 0) || (p0 != pm1);
        int f1 = (p1 != p0);
        int tsum = f0 + f1;
        int ws = tsum;
        #pragma unroll
        for (int o = 1; o < 32; o <<= 1) {
            int y = __shfl_up_sync(0xffffffffu, ws, o);
            if (lane >= o) ws += y;
        }
        __shared__ int wt[32];
        if (lane == 31) wt[wid] = ws;
        __syncthreads();
        if (wid == 0) {
            int t = wt[lane];
            #pragma unroll
            for (int o = 1; o < 32; o <<= 1) {
                int y = __shfl_up_sync(0xffffffffu, t, o);
                if (lane >= o) t += y;
            }
            wt[lane] = t;
        }
        __syncthreads();
        int base = (wid ? wt[wid - 1] : 0) + (ws - tsum);
        int incl0 = base + f0;
        int incl1 = base + f0 + f1;
        if (f0) g_starts[b * NU + incl0 - 1] = i0;
        if (f1) g_starts[b * NU + incl1 - 1] = i1;
        int ns = wt[31];
        __syncthreads();
        for (int u = tid; u < NU; u += 1024) {
            if (u < ns) {
                int st = g_starts[b * NU + u];
                int en = (u + 1 < ns) ? g_starts[b * NU + u + 1] : NT;
                g_dur[b * NU + u] = en - st;
            } else {
                g_dur[b * NU + u] = 0;
            }
        }
        if (tid == 0) g_nseg[b] = ns;
    } else {
        int b = blk - NB;
        int c = threadIdx.x;
        __shared__ float gs[NC];
        if (c < NC) gs[c] = g[(size_t)b * NC + c];
        __syncthreads();
        if (c < NC) {
            float acc = 0.f;
            const float* row = cw + (size_t)c * NC;
            #pragma unroll 8
            for (int gi = 0; gi < NC; gi++) acc += row[gi] * gs[gi];
            g_cgv[b * NC + c] = acc + cb[c];
        }
    }
}

// ---------------- kernel 2: mean pool (4 channels / block) ----------------
__global__ __launch_bounds__(256) void k_pool(const float* __restrict__ ec,
                                              const float* __restrict__ ep) {
    int b  = blockIdx.y;
    int c0 = blockIdx.x * 4;
    bool isC = (c0 < NC);
    const float* base = isC ? ec + ((size_t)b * NC + c0) * NT
                            : ep + ((size_t)b * NC + (c0 - NC)) * NT;
    __shared__ float rows[4][NT];
    const float4* s4 = (const float4*)base;
    float4* r4 = (float4*)&rows[0][0];
    #pragma unroll
    for (int i = threadIdx.x; i < 4 * NT / 4; i += 256) r4[i] = s4[i];
    __syncthreads();
    int ns = g_nseg[b];
    for (int u = threadIdx.x; u < NU; u += 256) {
        float m[4] = {0.f, 0.f, 0.f, 0.f};
        if (u < ns) {
            int st = g_starts[b * NU + u];
            int d  = g_dur[b * NU + u];
            float inv = 1.f / (float)d;
            #pragma unroll
            for (int r = 0; r < 4; r++) {
                float s = 0.f;
                for (int i = 0; i < d; i++) s += rows[r][st + i];
                m[r] = s * inv;
            }
        }
        #pragma unroll
        for (int r = 0; r < 4; r++) {
            int cc = c0 + r;
            if (isC) {
                float cond = g_cgv[b * NC + cc];
                g_uc[((size_t)b * NC + cc) * NU + u] = m[r];
                g_x0[((size_t)b * NC + cc) * NU + u] = (u < ns) ? (m[r] + cond) : 0.f;
            } else {
                g_up[((size_t)b * NC + (cc - NC)) * NU + u] = m[r];
            }
        }
    }
}

// ---------------- conv GEMM via 3xTF32 mma.sync, M-split 2-CTA cluster, m32n32 warps ----------
// Cluster (2,1,1): rank owns rows rank*128..+127 of a 64-col tile (u0=(bx>>1)*64).
// Per CTA: 8 warps; warp w: wm=w&3 -> rows rank*128+wm*32..+31 (2 m16 frags),
// wn=w>>2 -> cols wn*32..+31 (4 n8 frags). 16 A-LDS + 16 B-LDS per 24 MMAs.
// Column LN/proj sums exchanged with the peer CTA via DSMEM.
// PHASE 0: X=g_x0, epilogue = bias+relu+LN1*mask -> g_x1 (own half rows)
// PHASE 1: X=g_x1, epilogue = bias+relu+LN2*mask -> proj -> ceil -> g_dpred
template<int PHASE>
__global__ __launch_bounds__(256, 2) __cluster_dims__(2, 1, 1)
void k_conv(const float* __restrict__ W,
            const float* __restrict__ bias,
            const float* __restrict__ gamma,
            const float* __restrict__ beta,
            const float* __restrict__ pw,
            const float* __restrict__ pb) {
    __shared__ float Ah[2][BK][AP];
    __shared__ float Al[2][BK][AP];
    __shared__ float Bh[2][BK][BP];
    __shared__ float Bl[2][BK][BP];
    __shared__ float redA[8][34];        // per-warp 32 local cols (+pad)
    __shared__ float redB[8][34];
    __shared__ float p1[64], p2[64];     // half-column partial sums (exchanged)
    __shared__ float pd[64];             // proj partial (phase 1 exchange)
    __shared__ float mvs[64], rvs[64];

    cg::cluster_group cluster = cg::this_cluster();
    unsigned rank = cluster.block_rank();
    unsigned peer = rank ^ 1u;

    int b  = blockIdx.y;
    int u0 = (blockIdx.x >> 1) * 64;
    int rbase = rank * 128;
    int tid = threadIdx.x;
    int w  = tid >> 5;
    int l  = tid & 31;
    int wm = w & 3;         // row group 0..3 -> rows wm*32..+31
    int wn = w >> 2;        // col group 0..1 -> cols wn*32..+31
    int gq = l >> 2;        // 0..7
    int tq = l & 3;         // 0..3
    const float* X = PHASE ? g_x1 : g_x0;
    const float* Xb = X + (size_t)b * NC * NU;

    float acc[2][4][4];
    #pragma unroll
    for (int i = 0; i < 2; i++)
        #pragma unroll
        for (int j = 0; j < 4; j++)
            #pragma unroll
            for (int r = 0; r < 4; r++) acc[i][j][r] = 0.f;

    // loaders: A: am=tid&127 (row in half), akh=tid>>7 (k-quad); B: bkk=tid>>5, bnn=(tid&31)*2
    int am  = tid & 127;
    int akh = tid >> 7;
    int bkk = tid >> 5;
    int bnn = (tid & 31) * 2;
    float4 aA;
    float  bv0, bv1;

    auto loadG = [&](int k0) {
        aA = *(const float4*)&W[(size_t)(rbase + am) * KTOT + k0 + akh * 4];
        int kg  = k0 + bkk;
        int c   = kg / 3;
        int tap = kg - 3 * c;
        const float* xr = Xb + (size_t)c * NU;
        int col = u0 + bnn + tap - 1;
        bv0 = (col >= 0 && col < NU) ? xr[col] : 0.f;
        int col1 = col + 1;
        bv1 = (col1 >= 0 && col1 < NU) ? xr[col1] : 0.f;
    };
    auto storeS = [&](int buf) {
        float wv[4] = {aA.x, aA.y, aA.z, aA.w};
        #pragma unroll
        for (int q = 0; q < 4; q++) {
            float hf = __uint_as_float(f2tf32(wv[q]));
            float lf = __uint_as_float(f2tf32(wv[q] - hf));
            Ah[buf][akh * 4 + q][am] = hf;
            Al[buf][akh * 4 + q][am] = lf;
        }
        float h0 = __uint_as_float(f2tf32(bv0));
        float l0 = __uint_as_float(f2tf32(bv0 - h0));
        float h1 = __uint_as_float(f2tf32(bv1));
        float l1 = __uint_as_float(f2tf32(bv1 - h1));
        Bh[buf][bkk][bnn] = h0;  Bh[buf][bkk][bnn + 1] = h1;
        Bl[buf][bkk][bnn] = l0;  Bl[buf][bkk][bnn + 1] = l1;
    };

    loadG(0);
    storeS(0);
    __syncthreads();

    for (int chunk = 0; chunk < NCHUNK; chunk++) {
        int buf = chunk & 1;
        if (chunk + 1 < NCHUNK) loadG((chunk + 1) * BK);

        unsigned ah[2][4], al[2][4];
        #pragma unroll
        for (int i = 0; i < 2; i++) {
            int mb = wm * 32 + i * 16 + gq;
            ah[i][0] = __float_as_uint(Ah[buf][tq][mb]);
            ah[i][1] = __float_as_uint(Ah[buf][tq][mb + 8]);
            ah[i][2] = __float_as_uint(Ah[buf][tq + 4][mb]);
            ah[i][3] = __float_as_uint(Ah[buf][tq + 4][mb + 8]);
            al[i][0] = __float_as_uint(Al[buf][tq][mb]);
            al[i][1] = __float_as_uint(Al[buf][tq][mb + 8]);
            al[i][2] = __float_as_uint(Al[buf][tq + 4][mb]);
            al[i][3] = __float_as_uint(Al[buf][tq + 4][mb + 8]);
        }
        #pragma unroll
        for (int j = 0; j < 4; j++) {
            int nb = wn * 32 + j * 8 + gq;
            unsigned bh0 = __float_as_uint(Bh[buf][tq][nb]);
            unsigned bh1 = __float_as_uint(Bh[buf][tq + 4][nb]);
            unsigned bl0 = __float_as_uint(Bl[buf][tq][nb]);
            unsigned bl1 = __float_as_uint(Bl[buf][tq + 4][nb]);
            mma_tf32(acc[0][j], ah[0], bh0, bh1);
            mma_tf32(acc[1][j], ah[1], bh0, bh1);
            mma_tf32(acc[0][j], ah[0], bl0, bl1);
            mma_tf32(acc[1][j], ah[1], bl0, bl1);
            mma_tf32(acc[0][j], al[0], bh0, bh1);
            mma_tf32(acc[1][j], al[1], bh0, bh1);
        }
        if (chunk + 1 < NCHUNK) storeS(buf ^ 1);
        __syncthreads();
    }

    // ---- epilogue ----
    // rows: f(i,0) = rbase + wm*32 + i*16 + gq, f(i,1) = +8
    // cols: cloc(j,s) = wn*32 + j*8 + 2*tq + s  (local within 64-tile)
    float bs[2][2];
    #pragma unroll
    for (int i = 0; i < 2; i++) {
        bs[i][0] = bias[rbase + wm * 32 + i * 16 + gq];
        bs[i][1] = bias[rbase + wm * 32 + i * 16 + gq + 8];
    }
    float s1[4][2], s2[4][2];
    #pragma unroll
    for (int j = 0; j < 4; j++) { s1[j][0] = s1[j][1] = s2[j][0] = s2[j][1] = 0.f; }
    #pragma unroll
    for (int i = 0; i < 2; i++)
        #pragma unroll
        for (int j = 0; j < 4; j++) {
            float x0 = fmaxf(acc[i][j][0] + bs[i][0], 0.f);
            float x1 = fmaxf(acc[i][j][1] + bs[i][0], 0.f);
            float x2 = fmaxf(acc[i][j][2] + bs[i][1], 0.f);
            float x3 = fmaxf(acc[i][j][3] + bs[i][1], 0.f);
            acc[i][j][0] = x0; acc[i][j][1] = x1;
            acc[i][j][2] = x2; acc[i][j][3] = x3;
            s1[j][0] += x0 + x2;  s1[j][1] += x1 + x3;
            s2[j][0] += x0 * x0 + x2 * x2;
            s2[j][1] += x1 * x1 + x3 * x3;
        }
    #pragma unroll
    for (int o = 4; o < 32; o <<= 1) {
        #pragma unroll
        for (int j = 0; j < 4; j++) {
            s1[j][0] += __shfl_xor_sync(0xffffffffu, s1[j][0], o);
            s1[j][1] += __shfl_xor_sync(0xffffffffu, s1[j][1], o);
            s2[j][0] += __shfl_xor_sync(0xffffffffu, s2[j][0], o);
            s2[j][1] += __shfl_xor_sync(0xffffffffu, s2[j][1], o);
        }
    }
    if (l < 4) {
        #pragma unroll
        for (int j = 0; j < 4; j++) {
            redA[w][j * 8 + 2 * l]     = s1[j][0];
            redA[w][j * 8 + 2 * l + 1] = s1[j][1];
            redB[w][j * 8 + 2 * l]     = s2[j][0];
            redB[w][j * 8 + 2 * l + 1] = s2[j][1];
        }
    }
    __syncthreads();
    if (tid < 64) {
        int wbase = (tid >> 5) * 4;      // warps covering this 32-col group
        int cl = tid & 31;
        float S1 = 0.f, S2 = 0.f;
        #pragma unroll
        for (int q = 0; q < 4; q++) { S1 += redA[wbase + q][cl]; S2 += redB[wbase + q][cl]; }
        p1[tid] = S1;
        p2[tid] = S2;
    }
    cluster.sync();
    if (tid < 64) {
        const float* pp1 = cluster.map_shared_rank(p1, peer);
        const float* pp2 = cluster.map_shared_rank(p2, peer);
        float S1 = p1[tid] + pp1[tid];
        float S2 = p2[tid] + pp2[tid];
        float m  = S1 * (1.f / 256.f);
        float vv = S2 * (1.f / 256.f) - m * m;
        mvs[tid] = m;
        rvs[tid] = 1.f / sqrtf(vv + EPS);
    }
    __syncthreads();

    int ns = g_nseg[b];
    float mn[4][2], rv[4][2], mk[4][2];
    #pragma unroll
    for (int j = 0; j < 4; j++) {
        int c0 = wn * 32 + j * 8 + 2 * tq;
        mn[j][0] = mvs[c0];     mn[j][1] = mvs[c0 + 1];
        rv[j][0] = rvs[c0];     rv[j][1] = rvs[c0 + 1];
        mk[j][0] = (u0 + c0 < ns) ? 1.f : 0.f;
        mk[j][1] = (u0 + c0 + 1 < ns) ? 1.f : 0.f;
    }

    if (PHASE == 0) {
        #pragma unroll
        for (int i = 0; i < 2; i++) {
            int f0 = rbase + wm * 32 + i * 16 + gq;
            float ga0 = gamma[f0], be0 = beta[f0];
            float ga1 = gamma[f0 + 8], be1 = beta[f0 + 8];
            #pragma unroll
            for (int j = 0; j < 4; j++) {
                int cc = u0 + wn * 32 + j * 8 + 2 * tq;
                float o0 = ((acc[i][j][0] - mn[j][0]) * rv[j][0] * ga0 + be0) * mk[j][0];
                float o1 = ((acc[i][j][1] - mn[j][1]) * rv[j][1] * ga0 + be0) * mk[j][1];
                float o2 = ((acc[i][j][2] - mn[j][0]) * rv[j][0] * ga1 + be1) * mk[j][0];
                float o3 = ((acc[i][j][3] - mn[j][1]) * rv[j][1] * ga1 + be1) * mk[j][1];
                *(float2*)&g_x1[((size_t)b * NF + f0) * NU + cc]     = make_float2(o0, o1);
                *(float2*)&g_x1[((size_t)b * NF + f0 + 8) * NU + cc] = make_float2(o2, o3);
            }
        }
        cluster.sync();   // peer smem lifetime guard
    } else {
        float dp[4][2];
        #pragma unroll
        for (int j = 0; j < 4; j++) { dp[j][0] = 0.f; dp[j][1] = 0.f; }
        #pragma unroll
        for (int i = 0; i < 2; i++) {
            int f0 = rbase + wm * 32 + i * 16 + gq;
            float ga0 = gamma[f0], be0 = beta[f0], pw0 = pw[f0];
            float ga1 = gamma[f0 + 8], be1 = beta[f0 + 8], pw1 = pw[f0 + 8];
            #pragma unroll
            for (int j = 0; j < 4; j++) {
                float n0 = ((acc[i][j][0] - mn[j][0]) * rv[j][0] * ga0 + be0) * mk[j][0];
                float n1 = ((acc[i][j][1] - mn[j][1]) * rv[j][1] * ga0 + be0) * mk[j][1];
                float n2 = ((acc[i][j][2] - mn[j][0]) * rv[j][0] * ga1 + be1) * mk[j][0];
                float n3 = ((acc[i][j][3] - mn[j][1]) * rv[j][1] * ga1 + be1) * mk[j][1];
                dp[j][0] += n0 * pw0 + n2 * pw1;
                dp[j][1] += n1 * pw0 + n3 * pw1;
            }
        }
        #pragma unroll
        for (int o = 4; o < 32; o <<= 1) {
            #pragma unroll
            for (int j = 0; j < 4; j++) {
                dp[j][0] += __shfl_xor_sync(0xffffffffu, dp[j][0], o);
                dp[j][1] += __shfl_xor_sync(0xffffffffu, dp[j][1], o);
            }
        }
        if (l < 4) {
            #pragma unroll
            for (int j = 0; j < 4; j++) {
                redA[w][j * 8 + 2 * l]     = dp[j][0];
                redA[w][j * 8 + 2 * l + 1] = dp[j][1];
            }
        }
        __syncthreads();
        if (tid < 64) {
            int wbase = (tid >> 5) * 4;
            int cl = tid & 31;
            float S = 0.f;
            #pragma unroll
            for (int q = 0; q < 4; q++) S += redA[wbase + q][cl];
            pd[tid] = S;
        }
        cluster.sync();
        if (rank == 0 && tid < 64) {
            const float* ppd = cluster.map_shared_rank(pd, peer);
            float S = pd[tid] + ppd[tid];
            int u = u0 + tid;
            float d = (u < ns) ? ceilf(S + pb[0]) : 0.f;
            g_dpred[b * NU + u] = (int)d;
        }
        cluster.sync();   // peer smem lifetime guard
    }
}

// ---------------- kernel 5: zero um2 row + umax + per-batch prefix scan + scatter ----------------
__global__ __launch_bounds__(512) void k_scan(int Tn) {
    int b = blockIdx.x;
    for (int p = threadIdx.x; p < Tn; p += 512)
        g_um2[b * Tn + p] = 0;
    if (b == 0 && threadIdx.x == 0) {
        int mx = 0;
        #pragma unroll
        for (int q = 0; q < NB; q++) mx = max(mx, g_nseg[q]);
        g_umax = mx;
    }
    __syncthreads();
    int u = threadIdx.x;
    int lane = u & 31, wid = u >> 5;
    int d = g_dpred[b * NU + u];
    int x = d;
    #pragma unroll
    for (int o = 1; o < 32; o <<= 1) {
        int y = __shfl_up_sync(0xffffffffu, x, o);
        if (lane >= o) x += y;
    }
    __shared__ int wt[16];
    if (lane == 31) wt[wid] = x;
    __syncthreads();
    if (u < 16) {
        int t = wt[u];
        #pragma unroll
        for (int o = 1; o < 16; o <<= 1) {
            int y = __shfl_up_sync(0xffffu, t, o);
            if (u >= o) t += y;
        }
        wt[u] = t;
    }
    __syncthreads();
    int csum = x + (wid ? wt[wid - 1] : 0);
    int prev = csum - d;
    int lo = prev > 0 ? prev : 0;
    int hi = csum < Tn ? csum : Tn;
    for (int p = lo; p < hi; p++)
        atomicAdd(&g_um2[b * Tn + p], u + 1);
}

// ---------------- kernel 6: expand + interp -> output ----------------
__global__ __launch_bounds__(256) void k_out(const float* __restrict__ mel,
                                             float* __restrict__ out,
                                             int Tn, int total) {
    int i = blockIdx.x * blockDim.x + threadIdx.x;
    if (i >= total) return;
    int perb = NOUTC * Tn;
    int b = i / perb;
    int r = i - b * perb;
    int ch = r / Tn;
    int t = r - ch * Tn;
    if (ch < 2 * NC) {
        int v = g_um2[b * Tn + t];
        int um = g_umax;
        int idx = v < um ? v : um;   // jax gather clamp semantics
        float val = 0.f;
        if (idx > 0) {
            const float* P = (ch < NC) ? g_uc : g_up;
            int c = (ch < NC) ? ch : ch - NC;
            val = P[((size_t)b * NC + c) * NU + idx - 1];
        }
        out[i] = val;
    } else {
        int mch = ch - 2 * NC;
        float scale = (float)(2048.0 / (double)Tn);
        float src = ((float)t + 0.5f) * scale - 0.5f;
        src = fminf(fmaxf(src, 0.f), (float)(NT - 1));
        int i0 = (int)floorf(src);
        int i1 = i0 + 1 < NT - 1 ? i0 + 1 : NT - 1;
        float w = src - (float)i0;
        const float* mr = mel + ((size_t)b * NMEL + mch) * NT;
        out[i] = mr[i0] * (1.f - w) + mr[i1] * w;
    }
}

// ---------------- launch ----------------
extern "C" void kernel_launch(void* const* d_in, const int* in_sizes, int n_in,
                              void* d_out, int out_size) {
    const float* emb_c  = (const float*)d_in[0];
    const float* emb_p  = (const float*)d_in[1];
    const float* mel    = (const float*)d_in[2];
    const float* g      = (const float*)d_in[3];
    const float* c1w    = (const float*)d_in[4];
    const float* c1b    = (const float*)d_in[5];
    const float* l1g    = (const float*)d_in[6];
    const float* l1b    = (const float*)d_in[7];
    const float* c2w    = (const float*)d_in[8];
    const float* c2b    = (const float*)d_in[9];
    const float* l2g    = (const float*)d_in[10];
    const float* l2b    = (const float*)d_in[11];
    const float* pw     = (const float*)d_in[12];
    const float* pb     = (const float*)d_in[13];
    const float* cw     = (const float*)d_in[14];
    const float* cb     = (const float*)d_in[15];
    const int*   ph     = (const int*)d_in[16];
    float* out = (float*)d_out;

    int Tn = out_size / (NB * NOUTC);

    k_prep<<<2 * NB, 1024>>>(ph, g, cw, cb);
    k_pool<<<dim3(2 * NC / 4, NB), 256>>>(emb_c, emb_p);
    k_conv<0><<<dim3(2 * NU / 64, NB), 256>>>(c1w, c1b, l1g, l1b, pw, pb);
    k_conv<1><<<dim3(2 * NU / 64, NB), 256>>>(c2w, c2b, l2g, l2b, pw, pb);
    k_scan<<<NB, NU>>>(Tn);
    k_out<<<(out_size + 255) / 256, 256>>>(mel, out, Tn, out_size);
}